// round 16
// baseline (speedup 1.0000x reference)
#include <cuda_runtime.h>
#include <cuda_fp16.h>
#include <cstdint>

// Problem dims (fixed)
#define BATCH   4
#define LENGTH  2048
#define DMODEL  1024
#define DINNER  2048
#define DSTATE  16
#define DTRANK  64
#define BL      (BATCH*LENGTH)        // 8192
#define D2      (2*DINNER)            // 4096
#define DBCW    (DTRANK + 2*DSTATE)   // 96

// ------------------- static scratch (no cudaMalloc allowed) -------------------
__device__ float g_xz[(size_t)BL * D2];
__device__ float g_xc[(size_t)BL * DINNER];
__device__ float g_dbc[(size_t)BL * DBCW];
__device__ float g_delta[(size_t)BL * DINNER];

__device__ __half g_xh  [(size_t)BL*DMODEL];
__device__ __half g_winh[(size_t)D2*DMODEL];
__device__ __half g_xch [(size_t)BL*DINNER],   g_xcl [(size_t)BL*DINNER];
__device__ __half g_wxh [(size_t)DBCW*DINNER];
__device__ __half g_dth [(size_t)BL*DTRANK],   g_dtl [(size_t)BL*DTRANK];
__device__ __half g_wdth[(size_t)DINNER*DTRANK];
__device__ __half g_yh  [(size_t)BL*DINNER];
__device__ __half g_wouth[(size_t)DMODEL*DINNER];

// ------------------------------ PTX helpers ------------------------------
__device__ __forceinline__ uint32_t s2u(const void* p) {
    uint32_t a;
    asm("{ .reg .u64 t; cvta.to.shared.u64 t, %1; cvt.u32.u64 %0, t; }" : "=r"(a) : "l"(p));
    return a;
}
#define CP16(d, g) \
    asm volatile("cp.async.cg.shared.global [%0], [%1], 16;" :: "r"(d), "l"(g))
#define CP16Z(d, g, v) \
    asm volatile("cp.async.cg.shared.global [%0], [%1], 16, %2;" :: "r"(d), "l"(g), "r"(v))
#define CP_COMMIT() asm volatile("cp.async.commit_group;" ::: "memory")
#define CP_WAIT1()  asm volatile("cp.async.wait_group 1;" ::: "memory")

#define LDSM4(r, a) \
    asm volatile("ldmatrix.sync.aligned.m8n8.x4.shared.b16 {%0,%1,%2,%3}, [%4];" \
        : "=r"((r)[0]), "=r"((r)[1]), "=r"((r)[2]), "=r"((r)[3]) : "r"(a))

#define MMA16816(c, a, b0, b1) \
    asm volatile("mma.sync.aligned.m16n8k16.row.col.f32.f16.f16.f32 " \
        "{%0,%1,%2,%3}, {%4,%5,%6,%7}, {%8,%9}, {%0,%1,%2,%3};" \
        : "+f"((c)[0]), "+f"((c)[1]), "+f"((c)[2]), "+f"((c)[3]) \
        : "r"((a)[0]), "r"((a)[1]), "r"((a)[2]), "r"((a)[3]), "r"(b0), "r"(b1))

// ---------------------------------------------------------------------------
// Split-fp16 warp-MMA GEMM: C[m][n] = sum_k A[m][k]*B[n][k] (fp32 out)
// PASSES=2: A split (Ah+Al)·Bh.  PASSES=1: single Ah·Bh.
// CTA tile MTILE x NTILE (NTILE 128 or 256), BK=64 (144B-padded rows),
// 256 threads = 2 m-warps x 4 n-warps, warp tile (MTILE/2) x (NTILE/4).
// 3-buffer cp.async pipeline, wait_group 1, one __syncthreads per chunk.
// EPI: 0 plain, 1 softplus(v+bias[n]), 2 plain + fused fp16 dt-split (n<64).
// GUARD: bounds-check B rows / C cols against Nt.
// K<=64 (nit==1) kernels only touch stage 0 -> launch with 1*STG smem.
// ---------------------------------------------------------------------------
#define ROWB 144u    // 64 fp16 = 128B data + 16B pad

template<int MTILE, int NTILE, int PASSES, int EPI, bool GUARD>
__global__ __launch_bounds__(256, 1)
void tgemm(const __half* __restrict__ Ah, const __half* __restrict__ Al, int lda,
           const __half* __restrict__ Bh, int ldb,
           float* __restrict__ C, int ldc, int Nt, int K,
           const float* __restrict__ bias)
{
    constexpr uint32_t OFF_AL = (uint32_t)MTILE * ROWB;                 // if PASSES==2
    constexpr uint32_t OFF_B  = (uint32_t)PASSES * (uint32_t)MTILE * ROWB;
    constexpr uint32_t STG    = OFF_B + (uint32_t)NTILE * ROWB;
    constexpr int MI = MTILE / 32;        // m16 fragments per warp
    constexpr int NI = NTILE / 32;        // n8 fragment-pairs per warp

    extern __shared__ char smem[];
    const uint32_t sb = s2u(smem);

    const int tid = threadIdx.x;
    const int lid = tid & 31;
    const int wid = tid >> 5;
    const int wm0 = (wid & 1) * (MTILE / 2);
    const int wn0 = (wid >> 1) * (NTILE / 4);

    const int bm = blockIdx.y * MTILE;
    const int bn = blockIdx.x * NTILE;

    float acc[MI][NI][4];
#pragma unroll
    for (int i = 0; i < MI; i++)
#pragma unroll
        for (int j = 0; j < NI; j++)
#pragma unroll
            for (int k = 0; k < 4; k++) acc[i][j][k] = 0.f;

    auto ld_stage = [&](int s, int kc) {
        const uint32_t base = sb + (uint32_t)s * STG;
        const __half* pAh = Ah + (size_t)bm * lda + kc;
        const __half* pAl = (PASSES == 2) ? (Al + (size_t)bm * lda + kc) : pAh;
        const __half* pBh = Bh + (size_t)bn * ldb + kc;
#pragma unroll
        for (int i = 0; i < (MTILE * 8) / 256; ++i) {
            const int c   = tid + i * 256;
            const int row = c >> 3;
            const int ch  = (c & 7) * 16;
            const uint32_t o = (uint32_t)row * ROWB + (uint32_t)ch;
            CP16(base + o, (const char*)(pAh + (size_t)row * lda) + ch);
            if (PASSES == 2)
                CP16(base + OFF_AL + o, (const char*)(pAl + (size_t)row * lda) + ch);
        }
#pragma unroll
        for (int i = 0; i < (NTILE * 8) / 256; ++i) {
            const int c   = tid + i * 256;
            const int row = c >> 3;
            const int ch  = (c & 7) * 16;
            const uint32_t o = (uint32_t)row * ROWB + (uint32_t)ch;
            if (!GUARD) {
                CP16(base + OFF_B + o, (const char*)(pBh + (size_t)row * ldb) + ch);
            } else {
                const uint32_t v = ((bn + row) < Nt) ? 16u : 0u;
                CP16Z(base + OFF_B + o, (const char*)(pBh + (size_t)row * ldb) + ch, v);
            }
        }
    };

    const uint32_t arow  = (uint32_t)(wm0 + (lid & 15));
    const uint32_t akoff = (uint32_t)((lid >> 4) << 3);
    const uint32_t brow  = (uint32_t)(wn0 + ((lid >> 4) << 3) + (lid & 7));
    const uint32_t bkoff = (uint32_t)(((lid >> 3) & 1) << 3);

    auto compute = [&](int s) {
        const uint32_t aB = sb + (uint32_t)s * STG;
        const uint32_t bB = aB + OFF_B;
#pragma unroll
        for (int kk = 0; kk < 4; ++kk) {              // 4 x k16 per BK=64
            uint32_t bh[NI/2][4];
#pragma unroll
            for (int bi = 0; bi < NI/2; bi++) {
                const uint32_t bd = bB + (brow + bi*16) * ROWB + (bkoff + kk*16) * 2u;
                LDSM4(bh[bi], bd);
            }
#pragma unroll
            for (int mi = 0; mi < MI; mi++) {
                uint32_t ah[4], al[4];
                const uint32_t ad = aB + (arow + mi*16) * ROWB + (akoff + kk*16) * 2u;
                LDSM4(ah, ad);
                if (PASSES == 2) LDSM4(al, ad + OFF_AL);
#pragma unroll
                for (int nt = 0; nt < NI; nt++) {
                    const uint32_t b0 = bh[nt>>1][(nt&1)*2], b1 = bh[nt>>1][(nt&1)*2+1];
                    MMA16816(acc[mi][nt], ah, b0, b1);
                    if (PASSES == 2) MMA16816(acc[mi][nt], al, b0, b1);
                }
            }
        }
    };

    const int nit = K >> 6;                 // BK=64 chunks (>=1)
    ld_stage(0, 0);
    CP_COMMIT();
    if (nit > 1) ld_stage(1, 64);
    CP_COMMIT();                            // (possibly empty group)
    for (int it = 0; it < nit; ++it) {
        CP_WAIT1();
        __syncthreads();
        if (it + 2 < nit) ld_stage((it + 2) % 3, (it + 2) * 64);
        CP_COMMIT();
        compute(it % 3);
    }

    const int g  = lid >> 2;
    const int tg = lid & 3;
#pragma unroll
    for (int mi = 0; mi < MI; mi++) {
#pragma unroll
        for (int nt = 0; nt < NI; nt++) {
            const int m = bm + wm0 + mi * 16 + g;
            const int n = bn + wn0 + nt * 8 + 2 * tg;
            if (GUARD && n >= Nt) continue;
            float v0 = acc[mi][nt][0], v1 = acc[mi][nt][1];
            float v2 = acc[mi][nt][2], v3 = acc[mi][nt][3];
            if (EPI == 1) {
                const float b0 = bias[n], b1 = bias[n + 1];
                v0 += b0; v1 += b1; v2 += b0; v3 += b1;
                v0 = (v0 > 20.f) ? v0 : log1pf(__expf(v0));
                v1 = (v1 > 20.f) ? v1 : log1pf(__expf(v1));
                v2 = (v2 > 20.f) ? v2 : log1pf(__expf(v2));
                v3 = (v3 > 20.f) ? v3 : log1pf(__expf(v3));
            }
            *(float2*)&C[(size_t)m * ldc + n]       = make_float2(v0, v1);
            *(float2*)&C[(size_t)(m + 8) * ldc + n] = make_float2(v2, v3);
            if (EPI == 2 && n < DTRANK) {
                __half h0 = __float2half_rn(v0), h1 = __float2half_rn(v1);
                __half h2 = __float2half_rn(v2), h3 = __float2half_rn(v3);
                __half l0 = __float2half_rn(v0 - __half2float(h0));
                __half l1 = __float2half_rn(v1 - __half2float(h1));
                __half l2 = __float2half_rn(v2 - __half2float(h2));
                __half l3 = __float2half_rn(v3 - __half2float(h3));
                *(__half2*)&g_dth[(size_t)m * DTRANK + n] = __half2(h0, h1);
                *(__half2*)&g_dtl[(size_t)m * DTRANK + n] = __half2(l0, l1);
                *(__half2*)&g_dth[(size_t)(m + 8) * DTRANK + n] = __half2(h2, h3);
                *(__half2*)&g_dtl[(size_t)(m + 8) * DTRANK + n] = __half2(l2, l3);
            }
        }
    }
}

// ---------------------------------------------------------------------------
// One launch: all fp32 -> fp16 conversions.
// ---------------------------------------------------------------------------
#define N0 (BL*DMODEL)
#define N1 (D2*DMODEL)
#define N2 (DBCW*DINNER)
#define N3 (DINNER*DTRANK)
#define N4 (DMODEL*DINNER)
#define NT5 (N0+N1+N2+N3+N4)

__global__ __launch_bounds__(256)
void cvt_split5(const float* __restrict__ s0, const float* __restrict__ s1,
                const float* __restrict__ s2, const float* __restrict__ s3,
                const float* __restrict__ s4)
{
    int idx = blockIdx.x * 256 + threadIdx.x;
    if (idx >= NT5) return;
    const float* src; __half* hi; int off;
    if      (idx < N0)          { src = s0; hi = g_xh;    off = idx; }
    else if (idx < N0+N1)       { src = s1; hi = g_winh;  off = idx - N0; }
    else if (idx < N0+N1+N2)    { src = s2; hi = g_wxh;   off = idx - N0-N1; }
    else if (idx < N0+N1+N2+N3) { src = s3; hi = g_wdth;  off = idx - N0-N1-N2; }
    else                        { src = s4; hi = g_wouth; off = idx - N0-N1-N2-N3; }
    hi[off] = __float2half_rn(src[off]);
}

// ---------------------------------------------------------------------------
// Causal depthwise conv (k=4) + bias + SiLU; emits fp32 xc AND split fp16 xc
// ---------------------------------------------------------------------------
__global__ __launch_bounds__(256)
void conv_silu_kernel(const float* __restrict__ conv_w, const float* __restrict__ conv_b)
{
    const size_t idx = (size_t)blockIdx.x * 256 + threadIdx.x;
    if (idx >= (size_t)BL * DINNER) return;
    const int d  = (int)(idx % DINNER);
    const size_t bl = idx / DINNER;
    const int l  = (int)(bl % LENGTH);
    const size_t brow = (bl - l) * (size_t)D2;

    float acc = conv_b[d];
    const float w0 = conv_w[d*4+0], w1 = conv_w[d*4+1];
    const float w2 = conv_w[d*4+2], w3 = conv_w[d*4+3];
    const float* base = g_xz + brow + d;
    if (l >= 3) acc += w0 * base[(size_t)(l-3)*D2];
    if (l >= 2) acc += w1 * base[(size_t)(l-2)*D2];
    if (l >= 1) acc += w2 * base[(size_t)(l-1)*D2];
    acc += w3 * base[(size_t)l*D2];

    float s = acc / (1.f + __expf(-acc));
    g_xc[idx] = s;
    __half h = __float2half_rn(s);
    g_xch[idx] = h;
    g_xcl[idx] = __float2half_rn(s - __half2float(h));
}

// ---------------------------------------------------------------------------
// Selective scan: windowed cp.async staging (validated R11/R13/R15).
// ---------------------------------------------------------------------------
#define SW 16
__global__ __launch_bounds__(128)
void scan_kernel(const float* __restrict__ A_raw, const float* __restrict__ Dvec)
{
    __shared__ __align__(16) float s_d [2][SW][16];
    __shared__ __align__(16) float s_x [2][SW][16];
    __shared__ __align__(16) float s_z [2][SW][16];
    __shared__ __align__(16) float s_bc[2][SW][32];

    const int tid = threadIdx.x;
    const int sub = tid & 7;
    const int ch  = tid >> 3;
    const int blk = blockIdx.x;
    const int b   = blk >> 7;
    const int c0  = (blk & 127) << 4;
    const int c   = c0 + ch;

    const float a0 = -__expf(A_raw[(2*sub+0)*DINNER + c]);
    const float a1 = -__expf(A_raw[(2*sub+1)*DINNER + c]);
    const float Dv = Dvec[c];

    const float* dbase  = g_delta + (size_t)b*LENGTH*DINNER + c0;
    const float* xbase  = g_xc    + (size_t)b*LENGTH*DINNER + c0;
    const float* zbase  = g_xz    + (size_t)b*LENGTH*D2 + DINNER + c0;
    const float* bcbase = g_dbc   + (size_t)b*LENGTH*DBCW + DTRANK;
    __half* yhp = g_yh + (size_t)b*LENGTH*DINNER + c;

    auto ld_win = [&](int s, int t0) {
        const int ttA = tid >> 2, qA = (tid & 3) * 4;
        if (tid < 64) {
            CP16(s2u(&s_d[s][ttA][qA]), dbase + (size_t)(t0 + ttA)*DINNER + qA);
            CP16(s2u(&s_z[s][ttA][qA]), zbase + (size_t)(t0 + ttA)*D2 + qA);
        } else {
            const int tt = (tid - 64) >> 2, q = ((tid - 64) & 3) * 4;
            CP16(s2u(&s_x[s][tt][q]), xbase + (size_t)(t0 + tt)*DINNER + q);
        }
        const int ttB = tid >> 3, qB = (tid & 7) * 4;
        CP16(s2u(&s_bc[s][ttB][qB]), bcbase + (size_t)(t0 + ttB)*DBCW + qB);
    };

    float h0 = 0.f, h1 = 0.f;
    const int NW = LENGTH / SW;

    ld_win(0, 0);    CP_COMMIT();
    ld_win(1, SW);   CP_COMMIT();

    for (int w = 0; w < NW; ++w) {
        CP_WAIT1();
        __syncthreads();
        const int buf = w & 1;
        const int t0  = w * SW;

#pragma unroll
        for (int tt = 0; tt < SW; ++tt) {
            const float d  = s_d[buf][tt][ch];
            const float xv = s_x[buf][tt][ch];
            const float2 Bv = *(const float2*)&s_bc[buf][tt][2*sub];
            const float2 Cv = *(const float2*)&s_bc[buf][tt][16 + 2*sub];
            const float dx = d * xv;

            h0 = fmaf(__expf(d * a0), h0, Bv.x * dx);
            h1 = fmaf(__expf(d * a1), h1, Bv.y * dx);

            float acc = Cv.x * h0 + Cv.y * h1;
            acc += __shfl_xor_sync(0xffffffffu, acc, 1);
            acc += __shfl_xor_sync(0xffffffffu, acc, 2);
            acc += __shfl_xor_sync(0xffffffffu, acc, 4);

            if (sub == 0) {
                const float z = s_z[buf][tt][ch];
                float y = (acc + Dv * xv) * (z / (1.f + __expf(-z)));
                yhp[(size_t)(t0 + tt) * DINNER] = __float2half_rn(y);
            }
        }

        __syncthreads();
        if (w + 2 < NW) ld_win(buf, (w + 2) * SW);
        CP_COMMIT();
    }
}

// ---------------------------------------------------------------------------
extern "C" void kernel_launch(void* const* d_in, const int* in_sizes, int n_in,
                              void* d_out, int out_size)
{
    const float* x      = (const float*)d_in[0];
    const float* W_in   = (const float*)d_in[1];
    const float* conv_w = (const float*)d_in[2];
    const float* conv_b = (const float*)d_in[3];
    const float* W_x    = (const float*)d_in[4];
    const float* W_dt   = (const float*)d_in[5];
    const float* b_dt   = (const float*)d_in[6];
    const float* A_raw  = (const float*)d_in[7];
    const float* Dvec   = (const float*)d_in[8];
    const float* W_out  = (const float*)d_in[9];
    float* out = (float*)d_out;

    float *p_xz, *p_dbc, *p_delta;
    __half *p_xh,*p_winh,*p_xch,*p_xcl,*p_wxh;
    __half *p_dth,*p_dtl,*p_wdth,*p_yh,*p_wouth;
    cudaGetSymbolAddress((void**)&p_xz,    g_xz);
    cudaGetSymbolAddress((void**)&p_dbc,   g_dbc);
    cudaGetSymbolAddress((void**)&p_delta, g_delta);
    cudaGetSymbolAddress((void**)&p_xh,    g_xh);
    cudaGetSymbolAddress((void**)&p_winh,  g_winh);
    cudaGetSymbolAddress((void**)&p_xch,   g_xch);
    cudaGetSymbolAddress((void**)&p_xcl,   g_xcl);
    cudaGetSymbolAddress((void**)&p_wxh,   g_wxh);
    cudaGetSymbolAddress((void**)&p_dth,   g_dth);
    cudaGetSymbolAddress((void**)&p_dtl,   g_dtl);
    cudaGetSymbolAddress((void**)&p_wdth,  g_wdth);
    cudaGetSymbolAddress((void**)&p_yh,    g_yh);
    cudaGetSymbolAddress((void**)&p_wouth, g_wouth);

    // stage bytes: (PASSES*MTILE + NTILE) * 144
    const int STG_BIG   = (128 + 256) * 144;        // 55296  (1-pass, 128x256)
    const int STG_2P64  = (128 + 128) * 144;        // 36864  (2-pass, 64x128)
    const int STG_2P128 = (256 + 128) * 144;        // 55296  (2-pass, 128x128)
    const int SMEM_BIG   = 3 * STG_BIG;             // 165888
    const int SMEM_2P64  = 3 * STG_2P64;            // 110592
    const int SMEM_2P128 = 1 * STG_2P128;           // 55296  (K=64 -> only stage 0)
    cudaFuncSetAttribute(tgemm<128,256,1,0,false>, cudaFuncAttributeMaxDynamicSharedMemorySize, SMEM_BIG);
    cudaFuncSetAttribute(tgemm< 64,128,2,2,true >, cudaFuncAttributeMaxDynamicSharedMemorySize, SMEM_2P64);
    cudaFuncSetAttribute(tgemm<128,128,2,1,false>, cudaFuncAttributeMaxDynamicSharedMemorySize, SMEM_2P128);

    // 0) all conversions in one launch
    cvt_split5<<<(NT5 + 255)/256, 256>>>(x, W_in, W_x, W_dt, W_out);

    // 1) xz = x @ W_in^T   (8192 x 4096, K=1024), 1-pass fp16, 128x256 tile
    tgemm<128,256,1,0,false><<<dim3(D2/256, BL/128), 256, SMEM_BIG>>>(
        p_xh, nullptr, DMODEL, p_winh, DMODEL, p_xz, D2, D2, DMODEL, nullptr);

    // 2) conv + silu (emits fp32 + split fp16 xc)
    conv_silu_kernel<<<(unsigned)(((size_t)BL*DINNER + 255)/256), 256>>>(conv_w, conv_b);

    // 3) dbc = xc @ W_x^T  (8192 x 96, K=2048), 2-pass, fused dt split
    tgemm<64,128,2,2,true><<<dim3(1, BL/64), 256, SMEM_2P64>>>(
        p_xch, p_xcl, DINNER, p_wxh, DINNER, p_dbc, DBCW, DBCW, DINNER, nullptr);

    // 4) delta = softplus(dt @ W_dt^T + b_dt)  (8192 x 2048, K=64), 2-pass
    tgemm<128,128,2,1,false><<<dim3(DINNER/128, BL/128), 256, SMEM_2P128>>>(
        p_dth, p_dtl, DTRANK, p_wdth, DTRANK, p_delta, DINNER, DINNER, DTRANK, b_dt);

    // 5) selective scan (windowed cp.async) -> single fp16 y
    scan_kernel<<<BATCH*128, 128>>>(A_raw, Dvec);

    // 6) out = y @ W_out^T (8192 x 1024, K=2048), 1-pass fp16, 128x256 tile
    tgemm<128,256,1,0,false><<<dim3(DMODEL/256, BL/128), 256, SMEM_BIG>>>(
        p_yh, nullptr, DINNER, p_wouth, DINNER, out, DMODEL, DMODEL, DINNER, nullptr);
}